// round 5
// baseline (speedup 1.0000x reference)
#include <cuda_runtime.h>
#include <math.h>

#define EPSV 1e-7f
#define PI_F 3.14159265358979323846f
#define MAXBN 12800
#define H 128
#define EMAX 128

typedef unsigned long long ull;

// ---- packed f32x2 helpers (sm_100+) --------------------------------------
__device__ __forceinline__ ull pack2(float a, float b) {
    ull r; asm("mov.b64 %0,{%1,%2};" : "=l"(r) : "f"(a), "f"(b)); return r;
}
__device__ __forceinline__ void unpack2(ull v, float& a, float& b) {
    asm("mov.b64 {%0,%1},%2;" : "=f"(a), "=f"(b) : "l"(v));
}
__device__ __forceinline__ ull fma2(ull a, ull b, ull c) {
    ull d; asm("fma.rn.f32x2 %0,%1,%2,%3;" : "=l"(d) : "l"(a), "l"(b), "l"(c)); return d;
}
__device__ __forceinline__ ull mul2(ull a, ull b) {
    ull d; asm("mul.rn.f32x2 %0,%1,%2;" : "=l"(d) : "l"(a), "l"(b)); return d;
}
__device__ __forceinline__ float ex2a(float x) {
    float r; asm("ex2.approx.f32 %0,%1;" : "=f"(r) : "f"(x)); return r;
}
__device__ __forceinline__ float rcpa(float x) {
    float r; asm("rcp.approx.f32 %0,%1;" : "=f"(r) : "f"(x)); return r;
}
__device__ __forceinline__ void lds_v2(const float* p, float& a, float& b) {
    asm("{ .reg .u64 t; cvta.to.shared.u64 t, %2; ld.shared.v2.f32 {%0,%1},[t]; }"
        : "=f"(a), "=f"(b) : "l"(p));
}

#define NL2E -1.4426950408889634f  // -log2(e)

// scratch (static __device__ — no runtime allocation)
__device__ float g_R[MAXBN * 9];
__device__ float g_cv[MAXBN * 3];
__device__ float g_hsum[(size_t)MAXBN * H];

// ---------------------------------------------------------------------------
// Kernel A: per-node rotation matrix + canonical velocity
// ---------------------------------------------------------------------------
__global__ void node_prep(const float* __restrict__ inputs, int BN) {
    int idx = blockIdx.x * blockDim.x + threadIdx.x;
    if (idx >= BN) return;
    const float* x = inputs + (size_t)idx * 6;
    float vx = x[3], vy = x[4], vz = x[5];
    float rho = sqrtf(vx * vx + vy * vy + vz * vz);
    float theta = atan2f(vy, vx);
    float st, ct;
    sincosf(theta, &st, &ct);
    float cpin = fminf(fmaxf(vz / (rho + EPSV), -1.f), 1.f);
    float phi = acosf(cpin);
    float sp, cp;
    sincosf(phi, &sp, &cp);
    float R0 = cp * ct, R1 = -st, R2 = sp * ct;
    float R3 = cp * st, R4 = ct, R5 = sp * st;
    float R6 = -sp, R7 = 0.f, R8 = cp;
    float* Rg = g_R + (size_t)idx * 9;
    Rg[0] = R0; Rg[1] = R1; Rg[2] = R2;
    Rg[3] = R3; Rg[4] = R4; Rg[5] = R5;
    Rg[6] = R6; Rg[7] = R7; Rg[8] = R8;
    float* cv = g_cv + (size_t)idx * 3;
    cv[0] = R0 * vx + R3 * vy + R6 * vz;
    cv[1] = R1 * vx + R4 * vy + R7 * vz;
    cv[2] = R2 * vx + R5 * vy + R8 * vz;
}

// dummy: shifts ncu's fixed -s 5 capture window onto edge_kernel
__global__ void tick_kernel() {}

// ---------------------------------------------------------------------------
// Kernel B: per (b, recv node) block.
// Phase 1: thread t computes edge t's 12 features, feature-major se[k][t].
// Phase 2: warp w handles its own 1/4 of the edges; each lane owns 4
//          channels as TWO f32x2 channel-pairs (weights packed in regs).
//          Features arrive as LDS.64 broadcasts (one per feature per edge
//          PAIR), duplicated via cheap MOVs, reused across 2 edges x 2
//          channel-pairs. 4x less crossbar replication than channel-per-
//          thread. Cross-warp partial reduction at the end.
// ---------------------------------------------------------------------------
__device__ __forceinline__ ull silu2_acc(ull z, ull nl2, ull acc) {
    ull u = mul2(z, nl2);
    float u0, u1; unpack2(u, u0, u1);
    ull r = pack2(rcpa(ex2a(u0) + 1.f), rcpa(ex2a(u1) + 1.f));
    return fma2(z, r, acc);
}

__global__ void __launch_bounds__(128, 5)
edge_kernel(const float* __restrict__ inputs,
            const float* __restrict__ W1,
            const float* __restrict__ b1,
            int N) {
    int bi = blockIdx.x;
    int b = bi / N;
    int i = bi - b * N;
    int t = threadIdx.x;

    __shared__ __align__(16) float se[12][EMAX];
    __shared__ __align__(16) float partial[4][H];

    const float* xi = inputs + (size_t)bi * 6;
    float pix = xi[0], piy = xi[1], piz = xi[2];
    const float* Ri = g_R + (size_t)bi * 9;
    float r0 = Ri[0], r1 = Ri[1], r2 = Ri[2];
    float r3 = Ri[3], r4 = Ri[4], r5 = Ri[5];
    float r6 = Ri[6], r7 = Ri[7], r8 = Ri[8];

    int Em = N - 1;
    int Em_pad = (Em + 7) & ~7;
    int chunk = Em_pad >> 2;  // even, since Em_pad is a multiple of 8

    if (t < Em) {
        int j = t + (t >= i ? 1 : 0);
        const float* xj = inputs + ((size_t)b * N + j) * 6;
        float relx = xj[0] - pix, rely = xj[1] - piy, relz = xj[2] - piz;
        float rrx = r0 * relx + r3 * rely + r6 * relz;
        float rry = r1 * relx + r4 * rely + r7 * relz;
        float rrz = r2 * relx + r5 * rely + r8 * relz;
        float dist = sqrtf(relx * relx + rely * rely + relz * relz);
        float rho_e = sqrtf(rrx * rrx + rry * rry + rrz * rrz);
        float theta_e = atan2f(rry, rrx);
        float phi_e = acosf(fminf(fmaxf(rrz / (rho_e + EPSV), -1.f), 1.f));
        const float* Rj = g_R + ((size_t)b * N + j) * 9;
        float q0 = Rj[0], q1 = Rj[1], q2 = Rj[2];
        float q3 = Rj[3], q4 = Rj[4], q5 = Rj[5];
        float q6 = Rj[6], q7 = Rj[7], q8 = Rj[8];
        float ro00 = r0 * q0 + r3 * q3 + r6 * q6;
        float ro10 = r1 * q0 + r4 * q3 + r7 * q6;
        float ro20 = r2 * q0 + r5 * q3 + r8 * q6;
        float ro21 = r2 * q1 + r5 * q4 + r8 * q7;
        float ro22 = r2 * q2 + r5 * q5 + r8 * q8;
        float e0 = atan2f(ro10, ro00) * (1.f / PI_F);
        float e1 = asinf(fminf(fmaxf(-ro20, -1.f), 1.f)) * (1.f / PI_F);
        float e2 = atan2f(ro21, ro22) * (1.f / PI_F);
        float vjx = xj[3], vjy = xj[4], vjz = xj[5];
        float rvx = r0 * vjx + r3 * vjy + r6 * vjz;
        float rvy = r1 * vjx + r4 * vjy + r7 * vjz;
        float rvz = r2 * vjx + r5 * vjy + r8 * vjz;
        se[0][t] = rrx;  se[1][t] = rry;   se[2][t] = rrz;
        se[3][t] = e0;   se[4][t] = e1;    se[5][t] = e2;
        se[6][t] = dist; se[7][t] = theta_e; se[8][t] = phi_e;
        se[9][t] = rvx;  se[10][t] = rvy;  se[11][t] = rvz;
    } else if (t < Em_pad) {
#pragma unroll
        for (int k = 0; k < 12; k++) se[k][t] = 0.f;
    }

    int w = t >> 5;
    int lane = t & 31;
    int c0 = lane * 4;

    // packed weights: two channel-pairs per lane (24 ull regs)
    ull wp0[12], wp1[12];
#pragma unroll
    for (int k = 0; k < 12; k++) {
        const float* Wk = W1 + k * H + c0;
        wp0[k] = pack2(Wk[0], Wk[1]);
        wp1[k] = pack2(Wk[2], Wk[3]);
    }
    const float* cv = g_cv + (size_t)bi * 3;
    float base[4];
#pragma unroll
    for (int g = 0; g < 4; g++) {
        int c = c0 + g;
        base[g] = b1[c] + cv[0] * W1[15 * H + c] + cv[1] * W1[16 * H + c] +
                  cv[2] * W1[17 * H + c];
    }
    ull bp0 = pack2(base[0], base[1]);
    ull bp1 = pack2(base[2], base[3]);
    const ull nl2 = pack2(NL2E, NL2E);

    __syncthreads();

    int jbeg = w * chunk;
    int jend = jbeg + chunk;
    ull acc0 = 0ULL, acc1 = 0ULL;
    for (int je = jbeg; je < jend; je += 2) {
        ull zA0 = bp0, zA1 = bp1, zB0 = bp0, zB1 = bp1;
#pragma unroll
        for (int k = 0; k < 12; k++) {
            float fa, fb;
            lds_v2(&se[k][je], fa, fb);
            ull da = pack2(fa, fa);
            ull db = pack2(fb, fb);
            zA0 = fma2(da, wp0[k], zA0);
            zA1 = fma2(da, wp1[k], zA1);
            zB0 = fma2(db, wp0[k], zB0);
            zB1 = fma2(db, wp1[k], zB1);
        }
        acc0 = silu2_acc(zA0, nl2, acc0);
        acc1 = silu2_acc(zA1, nl2, acc1);
        acc0 = silu2_acc(zB0, nl2, acc0);
        acc1 = silu2_acc(zB1, nl2, acc1);
    }

    float h0, h1, h2, h3;
    unpack2(acc0, h0, h1);
    unpack2(acc1, h2, h3);
    // padding correction (zero-feature edges contribute silu(base))
    int lo = jbeg > Em ? jbeg : Em;
    int npad = jend - lo;
    if (npad > 0) {
        float fn = (float)npad;
        h0 -= fn * (base[0] * rcpa(ex2a(base[0] * NL2E) + 1.f));
        h1 -= fn * (base[1] * rcpa(ex2a(base[1] * NL2E) + 1.f));
        h2 -= fn * (base[2] * rcpa(ex2a(base[2] * NL2E) + 1.f));
        h3 -= fn * (base[3] * rcpa(ex2a(base[3] * NL2E) + 1.f));
    }
    *(float4*)&partial[w][c0] = make_float4(h0, h1, h2, h3);
    __syncthreads();

    float hsum = partial[0][t] + partial[1][t] + partial[2][t] + partial[3][t];
    g_hsum[(size_t)bi * H + t] = hsum;
}

// ---------------------------------------------------------------------------
// Kernel C: node MLP, 8 nodes per block, packed-f32x2 gemv.
// ---------------------------------------------------------------------------
__device__ __forceinline__ void gemv8p(const float sh[8][H],
                                       const float* __restrict__ W, int t,
                                       float acc[8]) {
    ull a[8];
#pragma unroll
    for (int n = 0; n < 8; n++) a[n] = 0ULL;
    for (int m = 0; m < H; m += 4) {
        ull wp0 = pack2(W[(m + 0) * H + t], W[(m + 1) * H + t]);
        ull wp1 = pack2(W[(m + 2) * H + t], W[(m + 3) * H + t]);
#pragma unroll
        for (int n = 0; n < 8; n++) {
            ulonglong2 h = *(const ulonglong2*)&sh[n][m];
            a[n] = fma2(h.x, wp0, a[n]);
            a[n] = fma2(h.y, wp1, a[n]);
        }
    }
#pragma unroll
    for (int n = 0; n < 8; n++) {
        float x, y;
        unpack2(a[n], x, y);
        acc[n] = x + y;
    }
}

__global__ void node_mlp(const float* __restrict__ inputs,
                         const float* __restrict__ W2, const float* __restrict__ b2,
                         const float* __restrict__ Wr, const float* __restrict__ br,
                         const float* __restrict__ W3, const float* __restrict__ b3,
                         const float* __restrict__ W4, const float* __restrict__ b4,
                         const float* __restrict__ W5, const float* __restrict__ b5,
                         float* __restrict__ out, int BN, float inv_cnt) {
    int t = threadIdx.x;
    int n0 = blockIdx.x * 8;
    __shared__ __align__(16) float shA[8][H];
    __shared__ __align__(16) float shB[8][H];
    __shared__ float spred[8][6];

#pragma unroll
    for (int n = 0; n < 8; n++) {
        int node = n0 + n;
        shA[n][t] = (node < BN) ? g_hsum[(size_t)node * H + t] : 0.f;
    }
    __syncthreads();

    float acc[8];
    gemv8p(shA, W2, t, acc);

    float wr3 = Wr[3 * H + t], wr4 = Wr[4 * H + t], wr5 = Wr[5 * H + t];
    float bb = b2[t] + br[t];
#pragma unroll
    for (int n = 0; n < 8; n++) {
        int node = n0 + n;
        float aug = 0.f;
        if (node < BN) {
            const float* cv = g_cv + (size_t)node * 3;
            aug = acc[n] * inv_cnt + bb + cv[0] * wr3 + cv[1] * wr4 + cv[2] * wr5;
        }
        shB[n][t] = aug;
    }
    __syncthreads();

    gemv8p(shB, W3, t, acc);
    float bias3 = b3[t];
#pragma unroll
    for (int n = 0; n < 8; n++) shA[n][t] = fmaxf(acc[n] + bias3, 0.f);
    __syncthreads();

    gemv8p(shA, W4, t, acc);
    float bias4 = b4[t];
#pragma unroll
    for (int n = 0; n < 8; n++) shB[n][t] = fmaxf(acc[n] + bias4, 0.f);
    __syncthreads();

    // Epilogue: warp wn handles nodes 2wn (lanes 0-5) and 2wn+1 (lanes 16-21)
    int wn = t >> 5;
    int lane = t & 31;
    int half = lane >> 4;
    int l = lane & 15;
    int n = 2 * wn + half;
    int node = n0 + n;
    if (l < 6 && node < BN) {
        float a = b5[l];
        for (int m = 0; m < H; m++) a += shB[n][m] * W5[m * 6 + l];
        spred[n][l] = a;
    }
    __syncwarp();
    if (l < 6 && node < BN) {
        const float* R = g_R + (size_t)node * 9;
        int r = l % 3;
        int s = (l / 3) * 3;
        float gl = R[r * 3 + 0] * spred[n][s + 0] +
                   R[r * 3 + 1] * spred[n][s + 1] +
                   R[r * 3 + 2] * spred[n][s + 2];
        out[(size_t)node * 6 + l] = inputs[(size_t)node * 6 + l] + gl;
    }
}

// ---------------------------------------------------------------------------
extern "C" void kernel_launch(void* const* d_in, const int* in_sizes, int n_in,
                              void* d_out, int out_size) {
    const float* inputs = (const float*)d_in[0];
    const float* W1 = (const float*)d_in[1];
    const float* b1 = (const float*)d_in[2];
    const float* W2 = (const float*)d_in[3];
    const float* b2 = (const float*)d_in[4];
    const float* Wr = (const float*)d_in[5];
    const float* br = (const float*)d_in[6];
    const float* W3 = (const float*)d_in[7];
    const float* b3 = (const float*)d_in[8];
    const float* W4 = (const float*)d_in[9];
    const float* b4 = (const float*)d_in[10];
    const float* W5 = (const float*)d_in[11];
    const float* b5 = (const float*)d_in[12];

    int E = in_sizes[14];  // recv_edges count = N*(N-1)
    int N = (int)((1.0 + sqrt(1.0 + 4.0 * (double)E)) / 2.0 + 0.5);
    int BN = in_sizes[0] / 6;
    if (N < 2 || N > 128 || BN > MAXBN) return;
    float inv_cnt = 1.0f / (float)(N - 1);

    node_prep<<<(BN + 255) / 256, 256>>>(inputs, BN);
    edge_kernel<<<BN, H>>>(inputs, W1, b1, N);
    node_mlp<<<(BN + 7) / 8, H>>>(inputs, W2, b2, Wr, br, W3, b3, W4, b4,
                                  W5, b5, (float*)d_out, BN, inv_cnt);
    tick_kernel<<<1, 32>>>();  // 4 launches/call -> ncu -s 5 lands on edge_kernel
}

// round 6
// speedup vs baseline: 1.4177x; 1.4177x over previous
#include <cuda_runtime.h>
#include <math.h>

#define EPSV 1e-7f
#define PI_F 3.14159265358979323846f
#define MAXBN 12800
#define H 128
#define EMAX 128

typedef unsigned long long ull;

// ---- packed f32x2 helpers (sm_100+) --------------------------------------
__device__ __forceinline__ ull pack2(float a, float b) {
    ull r; asm("mov.b64 %0,{%1,%2};" : "=l"(r) : "f"(a), "f"(b)); return r;
}
__device__ __forceinline__ void unpack2(ull v, float& a, float& b) {
    asm("mov.b64 {%0,%1},%2;" : "=f"(a), "=f"(b) : "l"(v));
}
__device__ __forceinline__ ull fma2(ull a, ull b, ull c) {
    ull d; asm("fma.rn.f32x2 %0,%1,%2,%3;" : "=l"(d) : "l"(a), "l"(b), "l"(c)); return d;
}
__device__ __forceinline__ ull mul2(ull a, ull b) {
    ull d; asm("mul.rn.f32x2 %0,%1,%2;" : "=l"(d) : "l"(a), "l"(b)); return d;
}
__device__ __forceinline__ ull add2(ull a, ull b) {
    ull d; asm("add.rn.f32x2 %0,%1,%2;" : "=l"(d) : "l"(a), "l"(b)); return d;
}
__device__ __forceinline__ float tanha(float x) {
    float r; asm("tanh.approx.f32 %0,%1;" : "=f"(r) : "f"(x)); return r;
}

// scratch (static __device__ — no runtime allocation)
__device__ float g_R[MAXBN * 9];
__device__ float g_cv[MAXBN * 3];
__device__ float g_hsum[(size_t)MAXBN * H];

// ---------------------------------------------------------------------------
// Kernel A: per-node rotation matrix + canonical velocity (range version;
// launched 3x so edge_kernel sits at stream index 3 for the ncu window)
// ---------------------------------------------------------------------------
__global__ void node_prep(const float* __restrict__ inputs, int start, int end) {
    int idx = start + blockIdx.x * blockDim.x + threadIdx.x;
    if (idx >= end) return;
    const float* x = inputs + (size_t)idx * 6;
    float vx = x[3], vy = x[4], vz = x[5];
    float rho = sqrtf(vx * vx + vy * vy + vz * vz);
    float theta = atan2f(vy, vx);
    float st, ct;
    sincosf(theta, &st, &ct);
    float cpin = fminf(fmaxf(vz / (rho + EPSV), -1.f), 1.f);
    float phi = acosf(cpin);
    float sp, cp;
    sincosf(phi, &sp, &cp);
    float R0 = cp * ct, R1 = -st, R2 = sp * ct;
    float R3 = cp * st, R4 = ct, R5 = sp * st;
    float R6 = -sp, R7 = 0.f, R8 = cp;
    float* Rg = g_R + (size_t)idx * 9;
    Rg[0] = R0; Rg[1] = R1; Rg[2] = R2;
    Rg[3] = R3; Rg[4] = R4; Rg[5] = R5;
    Rg[6] = R6; Rg[7] = R7; Rg[8] = R8;
    float* cv = g_cv + (size_t)idx * 3;
    cv[0] = R0 * vx + R3 * vy + R6 * vz;
    cv[1] = R1 * vx + R4 * vy + R7 * vz;
    cv[2] = R2 * vx + R5 * vy + R8 * vz;
}

// ---------------------------------------------------------------------------
// Kernel B (R3 structure + tanh-based silu: 1 MUFU per element).
// silu(z) = 0.5z + 0.5z*tanh(0.5z)
// ---------------------------------------------------------------------------
__device__ __forceinline__ ull silu2_acc(ull z, ull half2c, ull acc) {
    ull zh = mul2(z, half2c);
    float a0, a1; unpack2(zh, a0, a1);
    ull t2 = pack2(tanha(a0), tanha(a1));
    acc = fma2(zh, t2, acc);
    return add2(acc, zh);
}

__global__ void edge_kernel(const float* __restrict__ inputs,
                            const float* __restrict__ W1,
                            const float* __restrict__ b1,
                            int N) {
    int bi = blockIdx.x;
    int b = bi / N;
    int i = bi - b * N;
    int t = threadIdx.x;

    __shared__ __align__(16) float se[12][EMAX];

    const float* xi = inputs + (size_t)bi * 6;
    float pix = xi[0], piy = xi[1], piz = xi[2];
    const float* Ri = g_R + (size_t)bi * 9;
    float r0 = Ri[0], r1 = Ri[1], r2 = Ri[2];
    float r3 = Ri[3], r4 = Ri[4], r5 = Ri[5];
    float r6 = Ri[6], r7 = Ri[7], r8 = Ri[8];

    int Em = N - 1;
    int Em_pad = (Em + 3) & ~3;

    if (t < Em) {
        int j = t + (t >= i ? 1 : 0);
        const float* xj = inputs + ((size_t)b * N + j) * 6;
        float relx = xj[0] - pix, rely = xj[1] - piy, relz = xj[2] - piz;
        float rrx = r0 * relx + r3 * rely + r6 * relz;
        float rry = r1 * relx + r4 * rely + r7 * relz;
        float rrz = r2 * relx + r5 * rely + r8 * relz;
        float dist = sqrtf(relx * relx + rely * rely + relz * relz);
        float rho_e = sqrtf(rrx * rrx + rry * rry + rrz * rrz);
        float theta_e = atan2f(rry, rrx);
        float phi_e = acosf(fminf(fmaxf(rrz / (rho_e + EPSV), -1.f), 1.f));
        const float* Rj = g_R + ((size_t)b * N + j) * 9;
        float q0 = Rj[0], q1 = Rj[1], q2 = Rj[2];
        float q3 = Rj[3], q4 = Rj[4], q5 = Rj[5];
        float q6 = Rj[6], q7 = Rj[7], q8 = Rj[8];
        float ro00 = r0 * q0 + r3 * q3 + r6 * q6;
        float ro10 = r1 * q0 + r4 * q3 + r7 * q6;
        float ro20 = r2 * q0 + r5 * q3 + r8 * q6;
        float ro21 = r2 * q1 + r5 * q4 + r8 * q7;
        float ro22 = r2 * q2 + r5 * q5 + r8 * q8;
        float e0 = atan2f(ro10, ro00) * (1.f / PI_F);
        float e1 = asinf(fminf(fmaxf(-ro20, -1.f), 1.f)) * (1.f / PI_F);
        float e2 = atan2f(ro21, ro22) * (1.f / PI_F);
        float vjx = xj[3], vjy = xj[4], vjz = xj[5];
        float rvx = r0 * vjx + r3 * vjy + r6 * vjz;
        float rvy = r1 * vjx + r4 * vjy + r7 * vjz;
        float rvz = r2 * vjx + r5 * vjy + r8 * vjz;
        se[0][t] = rrx;  se[1][t] = rry;   se[2][t] = rrz;
        se[3][t] = e0;   se[4][t] = e1;    se[5][t] = e2;
        se[6][t] = dist; se[7][t] = theta_e; se[8][t] = phi_e;
        se[9][t] = rvx;  se[10][t] = rvy;  se[11][t] = rvz;
    } else if (t < Em_pad) {
#pragma unroll
        for (int k = 0; k < 12; k++) se[k][t] = 0.f;
    }

    // per-channel W1 column, packed (broadcast into both f32x2 halves)
    ull w2[12];
#pragma unroll
    for (int k = 0; k < 12; k++) {
        float w = W1[k * H + t];
        w2[k] = pack2(w, w);
    }
    const float* cv = g_cv + (size_t)bi * 3;
    float base = b1[t] + cv[0] * W1[15 * H + t] + cv[1] * W1[16 * H + t] +
                 cv[2] * W1[17 * H + t];
    ull base2 = pack2(base, base);
    const ull half2c = pack2(0.5f, 0.5f);

    __syncthreads();

    ull hs2 = 0ULL;
    for (int je = 0; je < Em_pad; je += 4) {
        ull zA = base2, zB = base2;
#pragma unroll
        for (int k = 0; k < 12; k++) {
            ulonglong2 p = *(const ulonglong2*)&se[k][je];
            zA = fma2(p.x, w2[k], zA);
            zB = fma2(p.y, w2[k], zB);
        }
        hs2 = silu2_acc(zA, half2c, hs2);
        hs2 = silu2_acc(zB, half2c, hs2);
    }
    float h0, h1;
    unpack2(hs2, h0, h1);
    float hsum = h0 + h1;
    int npad = Em_pad - Em;
    if (npad) {
        float bh = 0.5f * base;
        float sb = bh + bh * tanha(bh);
        hsum -= (float)npad * sb;
    }
    g_hsum[(size_t)bi * H + t] = hsum;
}

// ---------------------------------------------------------------------------
// Kernel C: node MLP, 4 nodes per block, packed-f32x2 gemv (R3 version).
// ---------------------------------------------------------------------------
__device__ __forceinline__ void gemv4p(const float sh[4][H],
                                       const float* __restrict__ W, int t,
                                       float acc[4]) {
    ull a0 = 0ULL, a1 = 0ULL, a2 = 0ULL, a3 = 0ULL;
    for (int m = 0; m < H; m += 4) {
        ull wp0 = pack2(W[(m + 0) * H + t], W[(m + 1) * H + t]);
        ull wp1 = pack2(W[(m + 2) * H + t], W[(m + 3) * H + t]);
        ulonglong2 h0 = *(const ulonglong2*)&sh[0][m];
        ulonglong2 h1 = *(const ulonglong2*)&sh[1][m];
        ulonglong2 h2 = *(const ulonglong2*)&sh[2][m];
        ulonglong2 h3 = *(const ulonglong2*)&sh[3][m];
        a0 = fma2(h0.x, wp0, a0); a0 = fma2(h0.y, wp1, a0);
        a1 = fma2(h1.x, wp0, a1); a1 = fma2(h1.y, wp1, a1);
        a2 = fma2(h2.x, wp0, a2); a2 = fma2(h2.y, wp1, a2);
        a3 = fma2(h3.x, wp0, a3); a3 = fma2(h3.y, wp1, a3);
    }
    float x, y;
    unpack2(a0, x, y); acc[0] = x + y;
    unpack2(a1, x, y); acc[1] = x + y;
    unpack2(a2, x, y); acc[2] = x + y;
    unpack2(a3, x, y); acc[3] = x + y;
}

__global__ void node_mlp(const float* __restrict__ inputs,
                         const float* __restrict__ W2, const float* __restrict__ b2,
                         const float* __restrict__ Wr, const float* __restrict__ br,
                         const float* __restrict__ W3, const float* __restrict__ b3,
                         const float* __restrict__ W4, const float* __restrict__ b4,
                         const float* __restrict__ W5, const float* __restrict__ b5,
                         float* __restrict__ out, int BN, float inv_cnt) {
    int t = threadIdx.x;
    int n0 = blockIdx.x * 4;
    __shared__ __align__(16) float shA[4][H];
    __shared__ __align__(16) float shB[4][H];
    __shared__ float spred[4][6];

#pragma unroll
    for (int n = 0; n < 4; n++) {
        int node = n0 + n;
        shA[n][t] = (node < BN) ? g_hsum[(size_t)node * H + t] : 0.f;
    }
    __syncthreads();

    float acc[4];
    gemv4p(shA, W2, t, acc);

    float wr3 = Wr[3 * H + t], wr4 = Wr[4 * H + t], wr5 = Wr[5 * H + t];
    float bb = b2[t] + br[t];
#pragma unroll
    for (int n = 0; n < 4; n++) {
        int node = n0 + n;
        float aug = 0.f;
        if (node < BN) {
            const float* cv = g_cv + (size_t)node * 3;
            aug = acc[n] * inv_cnt + bb + cv[0] * wr3 + cv[1] * wr4 + cv[2] * wr5;
        }
        shB[n][t] = aug;
    }
    __syncthreads();

    gemv4p(shB, W3, t, acc);
    float bias3 = b3[t];
#pragma unroll
    for (int n = 0; n < 4; n++) shA[n][t] = fmaxf(acc[n] + bias3, 0.f);
    __syncthreads();

    gemv4p(shA, W4, t, acc);
    float bias4 = b4[t];
#pragma unroll
    for (int n = 0; n < 4; n++) shB[n][t] = fmaxf(acc[n] + bias4, 0.f);
    __syncthreads();

    int wn = t >> 5;
    int lane = t & 31;
    int node = n0 + wn;
    if (lane < 6 && node < BN) {
        float a = b5[lane];
        for (int m = 0; m < H; m++) a += shB[wn][m] * W5[m * 6 + lane];
        spred[wn][lane] = a;
    }
    __syncwarp();
    if (lane < 6 && node < BN) {
        const float* R = g_R + (size_t)node * 9;
        int r = lane % 3;
        int s = (lane / 3) * 3;
        float gl = R[r * 3 + 0] * spred[wn][s + 0] +
                   R[r * 3 + 1] * spred[wn][s + 1] +
                   R[r * 3 + 2] * spred[wn][s + 2];
        out[(size_t)node * 6 + lane] = inputs[(size_t)node * 6 + lane] + gl;
    }
}

// ---------------------------------------------------------------------------
extern "C" void kernel_launch(void* const* d_in, const int* in_sizes, int n_in,
                              void* d_out, int out_size) {
    const float* inputs = (const float*)d_in[0];
    const float* W1 = (const float*)d_in[1];
    const float* b1 = (const float*)d_in[2];
    const float* W2 = (const float*)d_in[3];
    const float* b2 = (const float*)d_in[4];
    const float* Wr = (const float*)d_in[5];
    const float* br = (const float*)d_in[6];
    const float* W3 = (const float*)d_in[7];
    const float* b3 = (const float*)d_in[8];
    const float* W4 = (const float*)d_in[9];
    const float* b4 = (const float*)d_in[10];
    const float* W5 = (const float*)d_in[11];
    const float* b5 = (const float*)d_in[12];

    int E = in_sizes[14];  // recv_edges count = N*(N-1)
    int N = (int)((1.0 + sqrt(1.0 + 4.0 * (double)E)) / 2.0 + 0.5);
    int BN = in_sizes[0] / 6;
    if (N < 2 || N > 128 || BN > MAXBN) return;
    float inv_cnt = 1.0f / (float)(N - 1);

    // node_prep split in 3 so edge_kernel lands at stream index 3 (ncu window)
    int c = (BN + 2) / 3;
    int s1 = c, s2 = 2 * c;
    node_prep<<<(c + 255) / 256, 256>>>(inputs, 0, s1);
    node_prep<<<(c + 255) / 256, 256>>>(inputs, s1, s2);
    node_prep<<<(c + 255) / 256, 256>>>(inputs, s2, BN);
    edge_kernel<<<BN, H>>>(inputs, W1, b1, N);
    node_mlp<<<(BN + 3) / 4, H>>>(inputs, W2, b2, Wr, br, W3, b3, W4, b4,
                                  W5, b5, (float*)d_out, BN, inv_cnt);
}

// round 7
// speedup vs baseline: 1.5085x; 1.0640x over previous
#include <cuda_runtime.h>
#include <math.h>

#define EPSV 1e-7f
#define PI_F 3.14159265358979323846f
#define MAXBN 12800
#define H 128
#define EMAX 128

typedef unsigned long long ull;

// ---- packed f32x2 helpers (sm_100+) --------------------------------------
__device__ __forceinline__ ull pack2(float a, float b) {
    ull r; asm("mov.b64 %0,{%1,%2};" : "=l"(r) : "f"(a), "f"(b)); return r;
}
__device__ __forceinline__ void unpack2(ull v, float& a, float& b) {
    asm("mov.b64 {%0,%1},%2;" : "=f"(a), "=f"(b) : "l"(v));
}
__device__ __forceinline__ ull fma2(ull a, ull b, ull c) {
    ull d; asm("fma.rn.f32x2 %0,%1,%2,%3;" : "=l"(d) : "l"(a), "l"(b), "l"(c)); return d;
}
__device__ __forceinline__ ull mul2(ull a, ull b) {
    ull d; asm("mul.rn.f32x2 %0,%1,%2;" : "=l"(d) : "l"(a), "l"(b)); return d;
}
__device__ __forceinline__ ull add2(ull a, ull b) {
    ull d; asm("add.rn.f32x2 %0,%1,%2;" : "=l"(d) : "l"(a), "l"(b)); return d;
}
__device__ __forceinline__ float tanha(float x) {
    float r; asm("tanh.approx.f32 %0,%1;" : "=f"(r) : "f"(x)); return r;
}

// scratch (static __device__ — no runtime allocation)
__device__ float g_R[MAXBN * 9];
__device__ float g_cv[MAXBN * 3];
__device__ float g_hsum[(size_t)MAXBN * H];

// ---------------------------------------------------------------------------
// Kernel A: per-node rotation matrix + canonical velocity (range version;
// launched 3x so edge_kernel sits at stream index 3 for the ncu window)
// ---------------------------------------------------------------------------
__global__ void node_prep(const float* __restrict__ inputs, int start, int end) {
    int idx = start + blockIdx.x * blockDim.x + threadIdx.x;
    if (idx >= end) return;
    const float* x = inputs + (size_t)idx * 6;
    float vx = x[3], vy = x[4], vz = x[5];
    float rho = sqrtf(vx * vx + vy * vy + vz * vz);
    float theta = atan2f(vy, vx);
    float st, ct;
    sincosf(theta, &st, &ct);
    float cpin = fminf(fmaxf(vz / (rho + EPSV), -1.f), 1.f);
    float phi = acosf(cpin);
    float sp, cp;
    sincosf(phi, &sp, &cp);
    float R0 = cp * ct, R1 = -st, R2 = sp * ct;
    float R3 = cp * st, R4 = ct, R5 = sp * st;
    float R6 = -sp, R7 = 0.f, R8 = cp;
    float* Rg = g_R + (size_t)idx * 9;
    Rg[0] = R0; Rg[1] = R1; Rg[2] = R2;
    Rg[3] = R3; Rg[4] = R4; Rg[5] = R5;
    Rg[6] = R6; Rg[7] = R7; Rg[8] = R8;
    float* cv = g_cv + (size_t)idx * 3;
    cv[0] = R0 * vx + R3 * vy + R6 * vz;
    cv[1] = R1 * vx + R4 * vy + R7 * vz;
    cv[2] = R2 * vx + R5 * vy + R8 * vz;
}

// ---------------------------------------------------------------------------
// Kernel B: 64 threads/block, one block per (b, recv node).
// Stage: coalesced load of batch-row b's R (N*9) and inputs (N*6) to smem.
// Phase 1: thread t computes features of edges t and t+64 from smem.
// Phase 2: thread t owns channels t and t+64 (two dup-packed weight sets);
//          one LDS.128 of 4 edge-features now feeds 8 channel-elements:
//          half the broadcast LDS wavefronts of the 1-ch/thread layout.
// silu(z) = 0.5z + 0.5z*tanh(0.5z)  (1 MUFU/element)
// ---------------------------------------------------------------------------
__device__ __forceinline__ ull silu2_acc(ull z, ull half2c, ull acc) {
    ull zh = mul2(z, half2c);
    float a0, a1; unpack2(zh, a0, a1);
    ull t2 = pack2(tanha(a0), tanha(a1));
    acc = fma2(zh, t2, acc);
    return add2(acc, zh);
}

__global__ void edge_kernel(const float* __restrict__ inputs,
                            const float* __restrict__ W1,
                            const float* __restrict__ b1,
                            int N) {
    int bi = blockIdx.x;
    int b = bi / N;
    int i = bi - b * N;
    int t = threadIdx.x;

    __shared__ __align__(16) float se[12][EMAX];
    __shared__ __align__(16) float sR[EMAX * 9];
    __shared__ __align__(16) float sx[EMAX * 6];

    // coalesced stage of this batch-row's R and inputs
    {
        const float* gR = g_R + (size_t)b * N * 9;
        for (int idx = t; idx < N * 9; idx += 64) sR[idx] = gR[idx];
        const float* gx = inputs + (size_t)b * N * 6;
        for (int idx = t; idx < N * 6; idx += 64) sx[idx] = gx[idx];
    }
    __syncthreads();

    float pix = sx[i * 6 + 0], piy = sx[i * 6 + 1], piz = sx[i * 6 + 2];
    const float* Ri = sR + i * 9;
    float r0 = Ri[0], r1 = Ri[1], r2 = Ri[2];
    float r3 = Ri[3], r4 = Ri[4], r5 = Ri[5];
    float r6 = Ri[6], r7 = Ri[7], r8 = Ri[8];

    int Em = N - 1;
    int Em_pad = (Em + 3) & ~3;

    for (int e = t; e < Em_pad; e += 64) {
        if (e < Em) {
            int j = e + (e >= i ? 1 : 0);
            const float* xj = sx + j * 6;
            float relx = xj[0] - pix, rely = xj[1] - piy, relz = xj[2] - piz;
            float rrx = r0 * relx + r3 * rely + r6 * relz;
            float rry = r1 * relx + r4 * rely + r7 * relz;
            float rrz = r2 * relx + r5 * rely + r8 * relz;
            float dist = sqrtf(relx * relx + rely * rely + relz * relz);
            float rho_e = sqrtf(rrx * rrx + rry * rry + rrz * rrz);
            float theta_e = atan2f(rry, rrx);
            float phi_e = acosf(fminf(fmaxf(rrz / (rho_e + EPSV), -1.f), 1.f));
            const float* Rj = sR + j * 9;
            float q0 = Rj[0], q1 = Rj[1], q2 = Rj[2];
            float q3 = Rj[3], q4 = Rj[4], q5 = Rj[5];
            float q6 = Rj[6], q7 = Rj[7], q8 = Rj[8];
            float ro00 = r0 * q0 + r3 * q3 + r6 * q6;
            float ro10 = r1 * q0 + r4 * q3 + r7 * q6;
            float ro20 = r2 * q0 + r5 * q3 + r8 * q6;
            float ro21 = r2 * q1 + r5 * q4 + r8 * q7;
            float ro22 = r2 * q2 + r5 * q5 + r8 * q8;
            float e0 = atan2f(ro10, ro00) * (1.f / PI_F);
            float e1 = asinf(fminf(fmaxf(-ro20, -1.f), 1.f)) * (1.f / PI_F);
            float e2 = atan2f(ro21, ro22) * (1.f / PI_F);
            float vjx = xj[3], vjy = xj[4], vjz = xj[5];
            float rvx = r0 * vjx + r3 * vjy + r6 * vjz;
            float rvy = r1 * vjx + r4 * vjy + r7 * vjz;
            float rvz = r2 * vjx + r5 * vjy + r8 * vjz;
            se[0][e] = rrx;  se[1][e] = rry;   se[2][e] = rrz;
            se[3][e] = e0;   se[4][e] = e1;    se[5][e] = e2;
            se[6][e] = dist; se[7][e] = theta_e; se[8][e] = phi_e;
            se[9][e] = rvx;  se[10][e] = rvy;  se[11][e] = rvz;
        } else {
#pragma unroll
            for (int k = 0; k < 12; k++) se[k][e] = 0.f;
        }
    }

    // two channels per thread: c_a = t, c_b = t + 64
    int ca = t, cb = t + 64;
    ull wa[12], wb[12];
#pragma unroll
    for (int k = 0; k < 12; k++) {
        float u = W1[k * H + ca];
        float v = W1[k * H + cb];
        wa[k] = pack2(u, u);
        wb[k] = pack2(v, v);
    }
    const float* cv = g_cv + (size_t)bi * 3;
    float base_a = b1[ca] + cv[0] * W1[15 * H + ca] + cv[1] * W1[16 * H + ca] +
                   cv[2] * W1[17 * H + ca];
    float base_b = b1[cb] + cv[0] * W1[15 * H + cb] + cv[1] * W1[16 * H + cb] +
                   cv[2] * W1[17 * H + cb];
    ull bpa = pack2(base_a, base_a);
    ull bpb = pack2(base_b, base_b);
    const ull half2c = pack2(0.5f, 0.5f);

    __syncthreads();

    ull acc_a = 0ULL, acc_b = 0ULL;
    for (int je = 0; je < Em_pad; je += 4) {
        ull zxa = bpa, zya = bpa, zxb = bpb, zyb = bpb;
#pragma unroll
        for (int k = 0; k < 12; k++) {
            ulonglong2 p = *(const ulonglong2*)&se[k][je];
            zxa = fma2(p.x, wa[k], zxa);
            zya = fma2(p.y, wa[k], zya);
            zxb = fma2(p.x, wb[k], zxb);
            zyb = fma2(p.y, wb[k], zyb);
        }
        acc_a = silu2_acc(zxa, half2c, acc_a);
        acc_a = silu2_acc(zya, half2c, acc_a);
        acc_b = silu2_acc(zxb, half2c, acc_b);
        acc_b = silu2_acc(zyb, half2c, acc_b);
    }

    float a0, a1, b0v, b1v;
    unpack2(acc_a, a0, a1);
    unpack2(acc_b, b0v, b1v);
    float hs_a = a0 + a1;
    float hs_b = b0v + b1v;
    int npad = Em_pad - Em;
    if (npad) {
        float bh = 0.5f * base_a;
        hs_a -= (float)npad * (bh + bh * tanha(bh));
        float bh2 = 0.5f * base_b;
        hs_b -= (float)npad * (bh2 + bh2 * tanha(bh2));
    }
    g_hsum[(size_t)bi * H + ca] = hs_a;
    g_hsum[(size_t)bi * H + cb] = hs_b;
}

// ---------------------------------------------------------------------------
// Kernel C: node MLP, 8 nodes per block (halves W2/W3/W4 L2 re-read),
// packed-f32x2 gemv.
// ---------------------------------------------------------------------------
__device__ __forceinline__ void gemv8p(const float sh[8][H],
                                       const float* __restrict__ W, int t,
                                       float acc[8]) {
    ull a[8];
#pragma unroll
    for (int n = 0; n < 8; n++) a[n] = 0ULL;
    for (int m = 0; m < H; m += 4) {
        ull wp0 = pack2(W[(m + 0) * H + t], W[(m + 1) * H + t]);
        ull wp1 = pack2(W[(m + 2) * H + t], W[(m + 3) * H + t]);
#pragma unroll
        for (int n = 0; n < 8; n++) {
            ulonglong2 h = *(const ulonglong2*)&sh[n][m];
            a[n] = fma2(h.x, wp0, a[n]);
            a[n] = fma2(h.y, wp1, a[n]);
        }
    }
#pragma unroll
    for (int n = 0; n < 8; n++) {
        float x, y;
        unpack2(a[n], x, y);
        acc[n] = x + y;
    }
}

__global__ void node_mlp(const float* __restrict__ inputs,
                         const float* __restrict__ W2, const float* __restrict__ b2,
                         const float* __restrict__ Wr, const float* __restrict__ br,
                         const float* __restrict__ W3, const float* __restrict__ b3,
                         const float* __restrict__ W4, const float* __restrict__ b4,
                         const float* __restrict__ W5, const float* __restrict__ b5,
                         float* __restrict__ out, int BN, float inv_cnt) {
    int t = threadIdx.x;
    int n0 = blockIdx.x * 8;
    __shared__ __align__(16) float shA[8][H];
    __shared__ __align__(16) float shB[8][H];
    __shared__ float spred[8][6];

#pragma unroll
    for (int n = 0; n < 8; n++) {
        int node = n0 + n;
        shA[n][t] = (node < BN) ? g_hsum[(size_t)node * H + t] : 0.f;
    }
    __syncthreads();

    float acc[8];
    gemv8p(shA, W2, t, acc);

    float wr3 = Wr[3 * H + t], wr4 = Wr[4 * H + t], wr5 = Wr[5 * H + t];
    float bb = b2[t] + br[t];
#pragma unroll
    for (int n = 0; n < 8; n++) {
        int node = n0 + n;
        float aug = 0.f;
        if (node < BN) {
            const float* cv = g_cv + (size_t)node * 3;
            aug = acc[n] * inv_cnt + bb + cv[0] * wr3 + cv[1] * wr4 + cv[2] * wr5;
        }
        shB[n][t] = aug;
    }
    __syncthreads();

    gemv8p(shB, W3, t, acc);
    float bias3 = b3[t];
#pragma unroll
    for (int n = 0; n < 8; n++) shA[n][t] = fmaxf(acc[n] + bias3, 0.f);
    __syncthreads();

    gemv8p(shA, W4, t, acc);
    float bias4 = b4[t];
#pragma unroll
    for (int n = 0; n < 8; n++) shB[n][t] = fmaxf(acc[n] + bias4, 0.f);
    __syncthreads();

    // Epilogue: warp wn handles nodes 2wn (lanes 0-5) and 2wn+1 (lanes 16-21)
    int wn = t >> 5;
    int lane = t & 31;
    int half = lane >> 4;
    int l = lane & 15;
    int n = 2 * wn + half;
    int node = n0 + n;
    if (l < 6 && node < BN) {
        float a = b5[l];
        for (int m = 0; m < H; m++) a += shB[n][m] * W5[m * 6 + l];
        spred[n][l] = a;
    }
    __syncwarp();
    if (l < 6 && node < BN) {
        const float* R = g_R + (size_t)node * 9;
        int r = l % 3;
        int s = (l / 3) * 3;
        float gl = R[r * 3 + 0] * spred[n][s + 0] +
                   R[r * 3 + 1] * spred[n][s + 1] +
                   R[r * 3 + 2] * spred[n][s + 2];
        out[(size_t)node * 6 + l] = inputs[(size_t)node * 6 + l] + gl;
    }
}

// ---------------------------------------------------------------------------
extern "C" void kernel_launch(void* const* d_in, const int* in_sizes, int n_in,
                              void* d_out, int out_size) {
    const float* inputs = (const float*)d_in[0];
    const float* W1 = (const float*)d_in[1];
    const float* b1 = (const float*)d_in[2];
    const float* W2 = (const float*)d_in[3];
    const float* b2 = (const float*)d_in[4];
    const float* Wr = (const float*)d_in[5];
    const float* br = (const float*)d_in[6];
    const float* W3 = (const float*)d_in[7];
    const float* b3 = (const float*)d_in[8];
    const float* W4 = (const float*)d_in[9];
    const float* b4 = (const float*)d_in[10];
    const float* W5 = (const float*)d_in[11];
    const float* b5 = (const float*)d_in[12];

    int E = in_sizes[14];  // recv_edges count = N*(N-1)
    int N = (int)((1.0 + sqrt(1.0 + 4.0 * (double)E)) / 2.0 + 0.5);
    int BN = in_sizes[0] / 6;
    if (N < 2 || N > 128 || BN > MAXBN) return;
    float inv_cnt = 1.0f / (float)(N - 1);

    // node_prep split in 3 so edge_kernel lands at stream index 3 (ncu window)
    int c = (BN + 2) / 3;
    int s1 = c, s2 = 2 * c;
    node_prep<<<(c + 255) / 256, 256>>>(inputs, 0, s1);
    node_prep<<<(c + 255) / 256, 256>>>(inputs, s1, s2);
    node_prep<<<(c + 255) / 256, 256>>>(inputs, s2, BN);
    edge_kernel<<<BN, 64>>>(inputs, W1, b1, N);
    node_mlp<<<(BN + 7) / 8, H>>>(inputs, W2, b2, Wr, br, W3, b3, W4, b4,
                                  W5, b5, (float*)d_out, BN, inv_cnt);
}

// round 8
// speedup vs baseline: 1.6774x; 1.1120x over previous
#include <cuda_runtime.h>
#include <math.h>

#define EPSV 1e-7f
#define PI_F 3.14159265358979323846f
#define MAXBN 12800
#define H 128
#define EMAX 128

typedef unsigned long long ull;

// ---- packed f32x2 helpers (sm_100+) --------------------------------------
__device__ __forceinline__ ull pack2(float a, float b) {
    ull r; asm("mov.b64 %0,{%1,%2};" : "=l"(r) : "f"(a), "f"(b)); return r;
}
__device__ __forceinline__ void unpack2(ull v, float& a, float& b) {
    asm("mov.b64 {%0,%1},%2;" : "=f"(a), "=f"(b) : "l"(v));
}
__device__ __forceinline__ ull fma2(ull a, ull b, ull c) {
    ull d; asm("fma.rn.f32x2 %0,%1,%2,%3;" : "=l"(d) : "l"(a), "l"(b), "l"(c)); return d;
}
__device__ __forceinline__ float tanha(float x) {
    float r; asm("tanh.approx.f32 %0,%1;" : "=f"(r) : "f"(x)); return r;
}

// scratch (static __device__ — no runtime allocation)
__device__ float g_R[MAXBN * 9];
__device__ float g_cv[MAXBN * 3];
__device__ float g_hsum[(size_t)MAXBN * H];

// ---------------------------------------------------------------------------
// Kernel A: per-node rotation matrix + canonical velocity (range version;
// launched 3x so edge_kernel sits at the ncu capture slot)
// ---------------------------------------------------------------------------
__global__ void node_prep(const float* __restrict__ inputs, int start, int end) {
    int idx = start + blockIdx.x * blockDim.x + threadIdx.x;
    if (idx >= end) return;
    const float* x = inputs + (size_t)idx * 6;
    float vx = x[3], vy = x[4], vz = x[5];
    float rho = sqrtf(vx * vx + vy * vy + vz * vz);
    float theta = atan2f(vy, vx);
    float st, ct;
    sincosf(theta, &st, &ct);
    float cpin = fminf(fmaxf(vz / (rho + EPSV), -1.f), 1.f);
    float phi = acosf(cpin);
    float sp, cp;
    sincosf(phi, &sp, &cp);
    float R0 = cp * ct, R1 = -st, R2 = sp * ct;
    float R3 = cp * st, R4 = ct, R5 = sp * st;
    float R6 = -sp, R7 = 0.f, R8 = cp;
    float* Rg = g_R + (size_t)idx * 9;
    Rg[0] = R0; Rg[1] = R1; Rg[2] = R2;
    Rg[3] = R3; Rg[4] = R4; Rg[5] = R5;
    Rg[6] = R6; Rg[7] = R7; Rg[8] = R8;
    float* cv = g_cv + (size_t)idx * 3;
    cv[0] = R0 * vx + R3 * vy + R6 * vz;
    cv[1] = R1 * vx + R4 * vy + R7 * vz;
    cv[2] = R2 * vx + R5 * vy + R8 * vz;
}

// ---------------------------------------------------------------------------
// Kernel B: 64 threads/block, one block per (b, recv node).
// Weights & bias pre-scaled by 0.5 so the dot product yields z' = z/2:
//   silu(z) = z' + z'*tanh(z')
// Inner loop accumulates only z'*tanh(z') (1 fma-pipe op per f32x2 pair);
// the linear term Sum z' is reconstructed analytically from per-feature
// sums (sumF) computed once per block.
// ---------------------------------------------------------------------------
__device__ __forceinline__ ull tanh_acc(ull z, ull acc) {
    float a0, a1; unpack2(z, a0, a1);
    ull t2 = pack2(tanha(a0), tanha(a1));
    return fma2(z, t2, acc);
}

__global__ void edge_kernel(const float* __restrict__ inputs,
                            const float* __restrict__ W1,
                            const float* __restrict__ b1,
                            int N) {
    int bi = blockIdx.x;
    int b = bi / N;
    int i = bi - b * N;
    int t = threadIdx.x;

    __shared__ __align__(16) float se[12][EMAX];
    __shared__ __align__(16) float sR[EMAX * 9];
    __shared__ __align__(16) float sx[EMAX * 6];
    __shared__ float sP[12][4];

    // coalesced stage of this batch-row's R and inputs
    {
        const float* gR = g_R + (size_t)b * N * 9;
        for (int idx = t; idx < N * 9; idx += 64) sR[idx] = gR[idx];
        const float* gx = inputs + (size_t)b * N * 6;
        for (int idx = t; idx < N * 6; idx += 64) sx[idx] = gx[idx];
    }
    __syncthreads();

    float pix = sx[i * 6 + 0], piy = sx[i * 6 + 1], piz = sx[i * 6 + 2];
    const float* Ri = sR + i * 9;
    float r0 = Ri[0], r1 = Ri[1], r2 = Ri[2];
    float r3 = Ri[3], r4 = Ri[4], r5 = Ri[5];
    float r6 = Ri[6], r7 = Ri[7], r8 = Ri[8];

    int Em = N - 1;
    int Em_pad = (Em + 3) & ~3;

    for (int e = t; e < Em_pad; e += 64) {
        if (e < Em) {
            int j = e + (e >= i ? 1 : 0);
            const float* xj = sx + j * 6;
            float relx = xj[0] - pix, rely = xj[1] - piy, relz = xj[2] - piz;
            float rrx = r0 * relx + r3 * rely + r6 * relz;
            float rry = r1 * relx + r4 * rely + r7 * relz;
            float rrz = r2 * relx + r5 * rely + r8 * relz;
            float dist = sqrtf(relx * relx + rely * rely + relz * relz);
            float rho_e = sqrtf(rrx * rrx + rry * rry + rrz * rrz);
            float theta_e = atan2f(rry, rrx);
            float phi_e = acosf(fminf(fmaxf(rrz / (rho_e + EPSV), -1.f), 1.f));
            const float* Rj = sR + j * 9;
            float q0 = Rj[0], q1 = Rj[1], q2 = Rj[2];
            float q3 = Rj[3], q4 = Rj[4], q5 = Rj[5];
            float q6 = Rj[6], q7 = Rj[7], q8 = Rj[8];
            float ro00 = r0 * q0 + r3 * q3 + r6 * q6;
            float ro10 = r1 * q0 + r4 * q3 + r7 * q6;
            float ro20 = r2 * q0 + r5 * q3 + r8 * q6;
            float ro21 = r2 * q1 + r5 * q4 + r8 * q7;
            float ro22 = r2 * q2 + r5 * q5 + r8 * q8;
            float e0 = atan2f(ro10, ro00) * (1.f / PI_F);
            float e1 = asinf(fminf(fmaxf(-ro20, -1.f), 1.f)) * (1.f / PI_F);
            float e2 = atan2f(ro21, ro22) * (1.f / PI_F);
            float vjx = xj[3], vjy = xj[4], vjz = xj[5];
            float rvx = r0 * vjx + r3 * vjy + r6 * vjz;
            float rvy = r1 * vjx + r4 * vjy + r7 * vjz;
            float rvz = r2 * vjx + r5 * vjy + r8 * vjz;
            se[0][e] = rrx;  se[1][e] = rry;   se[2][e] = rrz;
            se[3][e] = e0;   se[4][e] = e1;    se[5][e] = e2;
            se[6][e] = dist; se[7][e] = theta_e; se[8][e] = phi_e;
            se[9][e] = rvx;  se[10][e] = rvy;  se[11][e] = rvz;
        } else {
#pragma unroll
            for (int k = 0; k < 12; k++) se[k][e] = 0.f;
        }
    }
    __syncthreads();

    // per-feature sums (threads 0-47: feature k, quarter p of the edge range)
    if (t < 48) {
        int k = t >> 2, p = t & 3;
        int lo = p * 32;
        int hi = (p + 1) * 32;
        if (hi > Em_pad) hi = Em_pad;
        float s = 0.f;
        for (int e = lo; e < hi; e++) s += se[k][e];
        sP[k][p] = s;
    }

    // two channels per thread: c_a = t, c_b = t + 64 ; weights HALVED
    int ca = t, cb = t + 64;
    ull wa[12], wb[12];
#pragma unroll
    for (int k = 0; k < 12; k++) {
        float u = 0.5f * W1[k * H + ca];
        float v = 0.5f * W1[k * H + cb];
        wa[k] = pack2(u, u);
        wb[k] = pack2(v, v);
    }
    const float* cv = g_cv + (size_t)bi * 3;
    float base_a = 0.5f * (b1[ca] + cv[0] * W1[15 * H + ca] +
                           cv[1] * W1[16 * H + ca] + cv[2] * W1[17 * H + ca]);
    float base_b = 0.5f * (b1[cb] + cv[0] * W1[15 * H + cb] +
                           cv[1] * W1[16 * H + cb] + cv[2] * W1[17 * H + cb]);
    ull bpa = pack2(base_a, base_a);
    ull bpb = pack2(base_b, base_b);

    ull acc_a = 0ULL, acc_b = 0ULL;
    for (int je = 0; je < Em_pad; je += 4) {
        ull zxa = bpa, zya = bpa, zxb = bpb, zyb = bpb;
#pragma unroll
        for (int k = 0; k < 12; k++) {
            ulonglong2 p = *(const ulonglong2*)&se[k][je];
            zxa = fma2(p.x, wa[k], zxa);
            zya = fma2(p.y, wa[k], zya);
            zxb = fma2(p.x, wb[k], zxb);
            zyb = fma2(p.y, wb[k], zyb);
        }
        acc_a = tanh_acc(zxa, acc_a);
        acc_a = tanh_acc(zya, acc_a);
        acc_b = tanh_acc(zxb, acc_b);
        acc_b = tanh_acc(zyb, acc_b);
    }

    __syncthreads();  // sP visible

    // analytic linear part: Sum_real z' = sumF . w' + Em * base'
    float lin_a = (float)Em * base_a;
    float lin_b = (float)Em * base_b;
#pragma unroll
    for (int k = 0; k < 12; k++) {
        float sF = sP[k][0] + sP[k][1] + sP[k][2] + sP[k][3];
        float wlo, whi, vlo, vhi;
        unpack2(wa[k], wlo, whi);
        unpack2(wb[k], vlo, vhi);
        lin_a += sF * wlo;
        lin_b += sF * vlo;
    }

    float a0, a1, b0v, b1v;
    unpack2(acc_a, a0, a1);
    unpack2(acc_b, b0v, b1v);
    float ts_a = a0 + a1;
    float ts_b = b0v + b1v;
    int npad = Em_pad - Em;
    if (npad) {  // padded edges contributed base'*tanh(base') to the tanh acc
        ts_a -= (float)npad * (base_a * tanha(base_a));
        ts_b -= (float)npad * (base_b * tanha(base_b));
    }
    g_hsum[(size_t)bi * H + ca] = lin_a + ts_a;
    g_hsum[(size_t)bi * H + cb] = lin_b + ts_b;
}

// ---------------------------------------------------------------------------
// Kernel C: node MLP, 16 nodes per block (halves W LDG traffic vs 8),
// packed-f32x2 gemv.
// ---------------------------------------------------------------------------
__device__ __forceinline__ void gemv16p(const float sh[16][H],
                                        const float* __restrict__ W, int t,
                                        float acc[16]) {
    ull a[16];
#pragma unroll
    for (int n = 0; n < 16; n++) a[n] = 0ULL;
    for (int m = 0; m < H; m += 4) {
        ull wp0 = pack2(W[(m + 0) * H + t], W[(m + 1) * H + t]);
        ull wp1 = pack2(W[(m + 2) * H + t], W[(m + 3) * H + t]);
#pragma unroll
        for (int n = 0; n < 16; n++) {
            ulonglong2 h = *(const ulonglong2*)&sh[n][m];
            a[n] = fma2(h.x, wp0, a[n]);
            a[n] = fma2(h.y, wp1, a[n]);
        }
    }
#pragma unroll
    for (int n = 0; n < 16; n++) {
        float x, y;
        unpack2(a[n], x, y);
        acc[n] = x + y;
    }
}

__global__ void node_mlp(const float* __restrict__ inputs,
                         const float* __restrict__ W2, const float* __restrict__ b2,
                         const float* __restrict__ Wr, const float* __restrict__ br,
                         const float* __restrict__ W3, const float* __restrict__ b3,
                         const float* __restrict__ W4, const float* __restrict__ b4,
                         const float* __restrict__ W5, const float* __restrict__ b5,
                         float* __restrict__ out, int BN, float inv_cnt) {
    int t = threadIdx.x;
    int n0 = blockIdx.x * 16;
    __shared__ __align__(16) float shA[16][H];
    __shared__ __align__(16) float shB[16][H];
    __shared__ float spred[16][6];

#pragma unroll
    for (int n = 0; n < 16; n++) {
        int node = n0 + n;
        shA[n][t] = (node < BN) ? g_hsum[(size_t)node * H + t] : 0.f;
    }
    __syncthreads();

    float acc[16];
    gemv16p(shA, W2, t, acc);

    float wr3 = Wr[3 * H + t], wr4 = Wr[4 * H + t], wr5 = Wr[5 * H + t];
    float bb = b2[t] + br[t];
#pragma unroll
    for (int n = 0; n < 16; n++) {
        int node = n0 + n;
        float aug = 0.f;
        if (node < BN) {
            const float* cv = g_cv + (size_t)node * 3;
            aug = acc[n] * inv_cnt + bb + cv[0] * wr3 + cv[1] * wr4 + cv[2] * wr5;
        }
        shB[n][t] = aug;
    }
    __syncthreads();

    gemv16p(shB, W3, t, acc);
    float bias3 = b3[t];
#pragma unroll
    for (int n = 0; n < 16; n++) shA[n][t] = fmaxf(acc[n] + bias3, 0.f);
    __syncthreads();

    gemv16p(shA, W4, t, acc);
    float bias4 = b4[t];
#pragma unroll
    for (int n = 0; n < 16; n++) shB[n][t] = fmaxf(acc[n] + bias4, 0.f);
    __syncthreads();

    // Epilogue: warp wn handles 4 nodes: lanes {0-5,8-13,16-21,24-29}
    int wn = t >> 5;
    int lane = t & 31;
    int l = lane & 7;
    int n = 4 * wn + (lane >> 3);
    int node = n0 + n;
    if (l < 6 && node < BN) {
        float a = b5[l];
        for (int m = 0; m < H; m++) a += shB[n][m] * W5[m * 6 + l];
        spred[n][l] = a;
    }
    __syncwarp();
    if (l < 6 && node < BN) {
        const float* R = g_R + (size_t)node * 9;
        int r = l % 3;
        int s = (l / 3) * 3;
        float gl = R[r * 3 + 0] * spred[n][s + 0] +
                   R[r * 3 + 1] * spred[n][s + 1] +
                   R[r * 3 + 2] * spred[n][s + 2];
        out[(size_t)node * 6 + l] = inputs[(size_t)node * 6 + l] + gl;
    }
}

// ---------------------------------------------------------------------------
extern "C" void kernel_launch(void* const* d_in, const int* in_sizes, int n_in,
                              void* d_out, int out_size) {
    const float* inputs = (const float*)d_in[0];
    const float* W1 = (const float*)d_in[1];
    const float* b1 = (const float*)d_in[2];
    const float* W2 = (const float*)d_in[3];
    const float* b2 = (const float*)d_in[4];
    const float* Wr = (const float*)d_in[5];
    const float* br = (const float*)d_in[6];
    const float* W3 = (const float*)d_in[7];
    const float* b3 = (const float*)d_in[8];
    const float* W4 = (const float*)d_in[9];
    const float* b4 = (const float*)d_in[10];
    const float* W5 = (const float*)d_in[11];
    const float* b5 = (const float*)d_in[12];

    int E = in_sizes[14];  // recv_edges count = N*(N-1)
    int N = (int)((1.0 + sqrt(1.0 + 4.0 * (double)E)) / 2.0 + 0.5);
    int BN = in_sizes[0] / 6;
    if (N < 2 || N > 128 || BN > MAXBN) return;
    float inv_cnt = 1.0f / (float)(N - 1);

    // node_prep split in 3 so edge_kernel lands in the ncu capture window
    int c = (BN + 2) / 3;
    int s1 = c, s2 = 2 * c;
    node_prep<<<(c + 255) / 256, 256>>>(inputs, 0, s1);
    node_prep<<<(c + 255) / 256, 256>>>(inputs, s1, s2);
    node_prep<<<(c + 255) / 256, 256>>>(inputs, s2, BN);
    edge_kernel<<<BN, 64>>>(inputs, W1, b1, N);
    node_mlp<<<(BN + 15) / 16, H>>>(inputs, W2, b2, Wr, br, W3, b3, W4, b4,
                                    W5, b5, (float*)d_out, BN, inv_cnt);
}